// round 9
// baseline (speedup 1.0000x reference)
#include <cuda_runtime.h>
#include <math.h>

// Problem sizes (fixed)
#define NR   65536
#define DIN  512
#define HD   128
#define DD   32
#define KC   1024
#define EPSBN 1e-5f

// ---------------- scratch (device globals; no allocations) ----------------
__device__ unsigned g_h1bf[NR * 64];     // encoder hidden pre-BN, bf16x2 (16.7 MB)
__device__ unsigned g_wtp[16 * 128 * 16];// W1^T bf16x2, per-chunk permuted (128KB)
__device__ int      g_topic[NR];
__device__ float    g_colsum[HD];
__device__ float    g_colsumsq[HD];
__device__ float    g_escale[HD];
__device__ float    g_eshift[HD];
__device__ float    g_cbnorm[KC];
__device__ unsigned g_cbbf[KC * 16];     // codebook bf16x2 packed (linear pairs)
__device__ float    g_cbproj[KC * HD];   // codebook @ dec_w1 + dec_b1
__device__ int      g_count[KC];
__device__ float    g_dscale[HD];
__device__ float    g_dshift[HD];
__device__ float    g_decoded[KC * DIN]; // decoded codewords (2 MB)
__device__ float    g_zloss;
__device__ float    g_recon;

// ---------------- bf16 helpers ----------------
__device__ __forceinline__ unsigned f2bf2(float lo, float hi) {
    unsigned r;
    asm("cvt.rn.bf16x2.f32 %0, %1, %2;" : "=r"(r) : "f"(hi), "f"(lo));
    return r;
}
__device__ __forceinline__ float bflo(unsigned u) { return __uint_as_float(u << 16); }
__device__ __forceinline__ float bfhi(unsigned u) { return __uint_as_float(u & 0xffff0000u); }

__device__ __forceinline__ void mma_bf16(float& c0, float& c1, float& c2, float& c3,
                                         unsigned a0, unsigned a1, unsigned a2, unsigned a3,
                                         unsigned b0, unsigned b1) {
    asm volatile(
        "mma.sync.aligned.m16n8k16.row.col.f32.bf16.bf16.f32 "
        "{%0,%1,%2,%3},{%4,%5,%6,%7},{%8,%9},{%0,%1,%2,%3};"
        : "+f"(c0), "+f"(c1), "+f"(c2), "+f"(c3)
        : "r"(a0), "r"(a1), "r"(a2), "r"(a3), "r"(b0), "r"(b1));
}

// permuted position of a local (0..15) bf16x2 pair within a 16-pair chunk row:
// lane t then loads ONE uint4 at 4t covering pairs {t, t+4, t+8, t+12}.
// pos(lp) = 4*(lp&3) + (lp>>2)   (self-inverse)

// ------ cbprep: init accumulators + norms + bf16 pack + cbproj (1 kernel) --
__global__ __launch_bounds__(128) void k_cbprep(const float* __restrict__ cb,
                                                const float* __restrict__ W1,
                                                const float* __restrict__ B1) {
    __shared__ float row[DD];
    int tid = threadIdx.x, k = blockIdx.x;
    if (tid == 0) g_count[k] = 0;
    if (k == 0) {
        if (tid < HD) { g_colsum[tid] = 0.f; g_colsumsq[tid] = 0.f; }
        if (tid == 0) { g_zloss = 0.f; g_recon = 0.f; }
    }
    if (tid < 8) ((float4*)row)[tid] = ((const float4*)cb)[k * 8 + tid];
    __syncthreads();
    if (tid < 32) {
        float v = row[tid];
        if (tid < 16) g_cbbf[k * 16 + tid] = f2bf2(row[2 * tid], row[2 * tid + 1]);
        float s = v * v;
#pragma unroll
        for (int off = 16; off; off >>= 1) s += __shfl_xor_sync(0xffffffffu, s, off);
        if (tid == 0) g_cbnorm[k] = s;
    }
    float acc = B1[tid];
#pragma unroll
    for (int d = 0; d < DD; d++) acc = fmaf(row[d], W1[d * HD + tid], acc);
    g_cbproj[k * HD + tid] = acc;
}

// ------ wprep: enc_w1 -> bf16x2 W^T, per-32-float-chunk permuted layout ----
__global__ __launch_bounds__(256) void k_wprep(const float* __restrict__ W) {
    __shared__ float sw[32][132];
    int kc = blockIdx.x, tid = threadIdx.x;
    int r = tid >> 3, c0 = (tid & 7) * 16;
    const float* Wp = W + (kc * 32 + r) * HD + c0;
#pragma unroll
    for (int i = 0; i < 4; i++) {
        float4 v = *(const float4*)(Wp + 4 * i);
        sw[r][c0 + 4 * i + 0] = v.x; sw[r][c0 + 4 * i + 1] = v.y;
        sw[r][c0 + 4 * i + 2] = v.z; sw[r][c0 + 4 * i + 3] = v.w;
    }
    __syncthreads();
#pragma unroll
    for (int i = 0; i < 8; i++) {
        int w = tid + i * 256;            // 0..2047
        int n = w >> 4, p = w & 15;
        int lp = 4 * (p & 3) + (p >> 2);  // pair stored at this position
        g_wtp[kc * 2048 + w] = f2bf2(sw[2 * lp][n], sw[2 * lp + 1][n]);
    }
}

// ------- GEMM1 (bf16 mma) + fused column stats: h1 = X@W + b --------------
// double-buffered; A/B fragments via single conflict-free LDS.128 each.
__global__ __launch_bounds__(256, 2) void k_gemm1(const float* __restrict__ X,
                                                  const float* __restrict__ Bb) {
    __shared__ unsigned xs[2][2048];    // [row][16 permuted pairs]
    __shared__ unsigned wts[2][2048];
    __shared__ float ss[HD], ssq[HD];
    int tid = threadIdx.x, lane = tid & 31, warp = tid >> 5;
    int g = lane >> 2, t = lane & 3;
    int row0 = blockIdx.x * 128;
    int m0 = (warp >> 1) * 32;
    int n0w = (warp & 1) * 64;

    if (tid < HD) { ss[tid] = 0.f; ssq[tid] = 0.f; }

    float c[2][8][4];
#pragma unroll
    for (int i = 0; i < 2; i++)
#pragma unroll
        for (int j = 0; j < 8; j++)
#pragma unroll
            for (int q = 0; q < 4; q++) c[i][j][q] = 0.f;

    int xr = tid >> 1, half = tid & 1;          // half = pairs 0-7 or 8-15
    const float* Xp = X + (row0 + xr) * DIN + half * 16;

    float4 xv[4];
    uint4 wv0, wv1;
#pragma unroll
    for (int i = 0; i < 4; i++) xv[i] = *(const float4*)(Xp + 4 * i);
    wv0 = ((const uint4*)g_wtp)[tid];
    wv1 = ((const uint4*)g_wtp)[tid + 256];

    // stage chunk 0
    {
        unsigned uu[8];
#pragma unroll
        for (int i = 0; i < 4; i++) {
            uu[2 * i]     = f2bf2(xv[i].x, xv[i].y);
            uu[2 * i + 1] = f2bf2(xv[i].z, xv[i].w);
        }
#pragma unroll
        for (int qp = 0; qp < 8; qp++) {
            int q2 = (qp + lane) & 7;
            int lp = half * 8 + q2;
            xs[0][xr * 16 + 4 * (lp & 3) + (lp >> 2)] = uu[q2];
        }
        ((uint4*)wts[0])[tid] = wv0;
        ((uint4*)wts[0])[tid + 256] = wv1;
    }
    __syncthreads();

    int p = 0;
    for (int kc = 0; kc < 16; kc++) {
        bool more = (kc + 1 < 16);
        if (more) {
#pragma unroll
            for (int i = 0; i < 4; i++) xv[i] = *(const float4*)(Xp + (kc + 1) * 32 + 4 * i);
            wv0 = ((const uint4*)g_wtp)[(kc + 1) * 512 + tid];
            wv1 = ((const uint4*)g_wtp)[(kc + 1) * 512 + tid + 256];
        }

        uint4 ua[2], ub[2];
#pragma unroll
        for (int mt = 0; mt < 2; mt++) {
            ua[mt] = *(const uint4*)&xs[p][(m0 + 16 * mt + g) * 16 + 4 * t];
            ub[mt] = *(const uint4*)&xs[p][(m0 + 16 * mt + 8 + g) * 16 + 4 * t];
        }
#pragma unroll
        for (int nt = 0; nt < 8; nt++) {
            uint4 vb = *(const uint4*)&wts[p][(n0w + 8 * nt + g) * 16 + 4 * t];
#pragma unroll
            for (int mt = 0; mt < 2; mt++) {
                mma_bf16(c[mt][nt][0], c[mt][nt][1], c[mt][nt][2], c[mt][nt][3],
                         ua[mt].x, ub[mt].x, ua[mt].y, ub[mt].y, vb.x, vb.y);
                mma_bf16(c[mt][nt][0], c[mt][nt][1], c[mt][nt][2], c[mt][nt][3],
                         ua[mt].z, ub[mt].z, ua[mt].w, ub[mt].w, vb.z, vb.w);
            }
        }

        if (more) {
            int q = p ^ 1;
            unsigned uu[8];
#pragma unroll
            for (int i = 0; i < 4; i++) {
                uu[2 * i]     = f2bf2(xv[i].x, xv[i].y);
                uu[2 * i + 1] = f2bf2(xv[i].z, xv[i].w);
            }
#pragma unroll
            for (int qp = 0; qp < 8; qp++) {
                int q2 = (qp + lane) & 7;
                int lp = half * 8 + q2;
                xs[q][xr * 16 + 4 * (lp & 3) + (lp >> 2)] = uu[q2];
            }
            ((uint4*)wts[q])[tid] = wv0;
            ((uint4*)wts[q])[tid + 256] = wv1;
        }
        __syncthreads();
        p ^= 1;
    }

    // epilogue: bias, bf16x2 store of h1 (linear pairs), column stats
    int r0 = row0 + m0 + g;
#pragma unroll
    for (int nt = 0; nt < 8; nt++) {
        int col = n0w + nt * 8 + 2 * t;
        int u = (n0w >> 1) + nt * 4 + t;
        float b0v = Bb[col], b1v = Bb[col + 1];
        float v00 = c[0][nt][0] + b0v, v01 = c[0][nt][1] + b1v;
        float v02 = c[0][nt][2] + b0v, v03 = c[0][nt][3] + b1v;
        float v10 = c[1][nt][0] + b0v, v11 = c[1][nt][1] + b1v;
        float v12 = c[1][nt][2] + b0v, v13 = c[1][nt][3] + b1v;
        g_h1bf[r0 * 64 + u]        = f2bf2(v00, v01);
        g_h1bf[(r0 + 8) * 64 + u]  = f2bf2(v02, v03);
        g_h1bf[(r0 + 16) * 64 + u] = f2bf2(v10, v11);
        g_h1bf[(r0 + 24) * 64 + u] = f2bf2(v12, v13);
        float s0 = v00 + v02 + v10 + v12;
        float s1 = v01 + v03 + v11 + v13;
        float q0 = v00 * v00 + v02 * v02 + v10 * v10 + v12 * v12;
        float q1 = v01 * v01 + v03 * v03 + v11 * v11 + v13 * v13;
#pragma unroll
        for (int off = 4; off <= 16; off <<= 1) {
            s0 += __shfl_xor_sync(0xffffffffu, s0, off);
            s1 += __shfl_xor_sync(0xffffffffu, s1, off);
            q0 += __shfl_xor_sync(0xffffffffu, q0, off);
            q1 += __shfl_xor_sync(0xffffffffu, q1, off);
        }
        if (g == 0) {
            atomicAdd(&ss[col],      s0);
            atomicAdd(&ss[col + 1],  s1);
            atomicAdd(&ssq[col],     q0);
            atomicAdd(&ssq[col + 1], q1);
        }
    }
    __syncthreads();
    if (tid < HD) {
        atomicAdd(&g_colsum[tid], ss[tid]);
        atomicAdd(&g_colsumsq[tid], ssq[tid]);
    }
}

__global__ void k_bnfin(const float* __restrict__ G, const float* __restrict__ BE) {
    int j = threadIdx.x;
    float mean = g_colsum[j] * (1.f / (float)NR);
    float var  = g_colsumsq[j] * (1.f / (float)NR) - mean * mean;
    float sc = G[j] * rsqrtf(var + EPSBN);
    g_escale[j] = sc;
    g_eshift[j] = BE[j] - mean * sc;
}

// ------ FUSED: z = relu(bn(h1)) @ W2 -> distance argmin (z never hits mem) -
// all fragments via LDS.128; argmin via index-packed fmin.
__global__ __launch_bounds__(512) void k_fused(const float* __restrict__ cb,
                                               const float* __restrict__ W2,
                                               const float* __restrict__ B2) {
    extern __shared__ unsigned fsm[];
    unsigned* cbs = fsm;                  // 1024 rows x 16 permuted pairs (64KB)
    unsigned* as4 = fsm + 16384;          // 4 chunks x 256 rows x 16 pairs (64KB)
    unsigned* wt4 = fsm + 32768;          // 4 chunks x 32 rows x 16 pairs (8KB)
    float* zsm = (float*)(fsm + 34816);   // 256 x 33 fp32 (33KB)
    float* cns = zsm + 8448;              // 1024 (4KB)

    int tid = threadIdx.x, lane = tid & 31, warp = tid >> 5;
    int g = lane >> 2, t = lane & 3;
    int row0 = blockIdx.x * 256;

    // stage W2 -> wt4 (8KB, scattered scalar fill)
#pragma unroll
    for (int i = 0; i < 4; i++) {
        int w = tid + i * 512;            // 0..2047
        int ch = w >> 9, rem = w & 511;
        int n = rem >> 4, pp = rem & 15;
        int lp = 4 * (pp & 3) + (pp >> 2);
        int k0 = 32 * ch + 2 * lp;
        wt4[w] = f2bf2(W2[k0 * DD + n], W2[(k0 + 1) * DD + n]);
    }
    // stage codebook -> cbs permuted
#pragma unroll
    for (int i = 0; i < 8; i++) {
        int e = tid + i * 512;            // uint4 index (4096)
        uint4 u = ((const uint4*)g_cbbf)[e];
        int n = e >> 2, i4 = e & 3;       // pairs 4*i4 .. 4*i4+3
        cbs[n * 16 + i4 + 0]  = u.x;      // pos = 4q + i4
        cbs[n * 16 + i4 + 4]  = u.y;
        cbs[n * 16 + i4 + 8]  = u.z;
        cbs[n * 16 + i4 + 12] = u.w;
    }
#pragma unroll
    for (int i = 0; i < 2; i++) cns[tid + i * 512] = g_cbnorm[tid + i * 512];
    // stage activations: bf16 h1 -> BN -> ReLU -> as4 permuted
#pragma unroll
    for (int i = 0; i < 8; i++) {
        int e = tid + i * 512;            // uint4 index (4096)
        int r = e >> 4, i4 = e & 15;      // pairs 4*i4..4*i4+3, ch = i4>>2
        uint4 u = *(const uint4*)&g_h1bf[(row0 + r) * 64 + 4 * i4];
        float4 sc0 = __ldg((const float4*)&g_escale[8 * i4]);
        float4 sc1 = __ldg((const float4*)&g_escale[8 * i4 + 4]);
        float4 sh0 = __ldg((const float4*)&g_eshift[8 * i4]);
        float4 sh1 = __ldg((const float4*)&g_eshift[8 * i4 + 4]);
        int ch = i4 >> 2, il = i4 & 3;
        unsigned* base = &as4[ch * 4096 + r * 16 + il];
        base[0]  = f2bf2(fmaxf(fmaf(bflo(u.x), sc0.x, sh0.x), 0.f),
                         fmaxf(fmaf(bfhi(u.x), sc0.y, sh0.y), 0.f));
        base[4]  = f2bf2(fmaxf(fmaf(bflo(u.y), sc0.z, sh0.z), 0.f),
                         fmaxf(fmaf(bfhi(u.y), sc0.w, sh0.w), 0.f));
        base[8]  = f2bf2(fmaxf(fmaf(bflo(u.z), sc1.x, sh1.x), 0.f),
                         fmaxf(fmaf(bfhi(u.z), sc1.y, sh1.y), 0.f));
        base[12] = f2bf2(fmaxf(fmaf(bflo(u.w), sc1.z, sh1.z), 0.f),
                         fmaxf(fmaf(bfhi(u.w), sc1.w, sh1.w), 0.f));
    }
    __syncthreads();

    // ---- gemm2: per-warp 16 rows, z[16 x 32] in C fragments ----
    int m0 = warp * 16;
    float c[4][4];
#pragma unroll
    for (int nt = 0; nt < 4; nt++)
#pragma unroll
        for (int q = 0; q < 4; q++) c[nt][q] = 0.f;
#pragma unroll
    for (int ch = 0; ch < 4; ch++) {
        uint4 ua = *(const uint4*)&as4[ch * 4096 + (m0 + g) * 16 + 4 * t];
        uint4 ub = *(const uint4*)&as4[ch * 4096 + (m0 + 8 + g) * 16 + 4 * t];
#pragma unroll
        for (int nt = 0; nt < 4; nt++) {
            uint4 vb = *(const uint4*)&wt4[ch * 512 + (nt * 8 + g) * 16 + 4 * t];
            mma_bf16(c[nt][0], c[nt][1], c[nt][2], c[nt][3],
                     ua.x, ub.x, ua.y, ub.y, vb.x, vb.y);
            mma_bf16(c[nt][0], c[nt][1], c[nt][2], c[nt][3],
                     ua.z, ub.z, ua.w, ub.w, vb.z, vb.w);
        }
    }
    // bias; fp32 copy to zsm; repack C-frags into dist A-frags
    int ra = m0 + g, rb = m0 + 8 + g;
    unsigned za[2][4];
#pragma unroll
    for (int nt = 0; nt < 4; nt++) {
        int col = nt * 8 + 2 * t;
        float b0v = B2[col], b1v = B2[col + 1];
        c[nt][0] += b0v; c[nt][1] += b1v; c[nt][2] += b0v; c[nt][3] += b1v;
        zsm[ra * 33 + col]     = c[nt][0];
        zsm[ra * 33 + col + 1] = c[nt][1];
        zsm[rb * 33 + col]     = c[nt][2];
        zsm[rb * 33 + col + 1] = c[nt][3];
    }
#pragma unroll
    for (int s = 0; s < 2; s++) {
        za[s][0] = f2bf2(c[2 * s][0],     c[2 * s][1]);
        za[s][1] = f2bf2(c[2 * s][2],     c[2 * s][3]);
        za[s][2] = f2bf2(c[2 * s + 1][0], c[2 * s + 1][1]);
        za[s][3] = f2bf2(c[2 * s + 1][2], c[2 * s + 1][3]);
    }
    __syncwarp();   // zsm rows of this warp written by its own lanes only

    // ---- distance sweep: index packed into low 10 mantissa bits, fmin ----
    float bd0 = 3.4e38f, bdh = 3.4e38f;
    int nb = g * 16 + 4 * t;
#pragma unroll 2
    for (int n0 = 0; n0 < KC / 8; n0++) {
        uint4 vb = *(const uint4*)&cbs[n0 * 128 + nb];
        float d0 = 0.f, d1 = 0.f, d2 = 0.f, d3 = 0.f;
        mma_bf16(d0, d1, d2, d3, za[0][0], za[0][1], za[0][2], za[0][3], vb.x, vb.y);
        mma_bf16(d0, d1, d2, d3, za[1][0], za[1][1], za[1][2], za[1][3], vb.z, vb.w);
        int col0 = n0 * 8 + 2 * t;
        float2 cn = *(const float2*)&cns[col0];
        float e0 = fmaf(d0, -2.f, cn.x), e1 = fmaf(d1, -2.f, cn.y);
        float f0 = fmaf(d2, -2.f, cn.x), f1 = fmaf(d3, -2.f, cn.y);
        bd0 = fminf(bd0, __uint_as_float((__float_as_uint(e0) & 0xfffffc00u) | col0));
        bd0 = fminf(bd0, __uint_as_float((__float_as_uint(e1) & 0xfffffc00u) | (col0 + 1)));
        bdh = fminf(bdh, __uint_as_float((__float_as_uint(f0) & 0xfffffc00u) | col0));
        bdh = fminf(bdh, __uint_as_float((__float_as_uint(f1) & 0xfffffc00u) | (col0 + 1)));
    }
#pragma unroll
    for (int off = 1; off <= 2; off <<= 1) {
        bd0 = fminf(bd0, __shfl_xor_sync(0xffffffffu, bd0, off));
        bdh = fminf(bdh, __shfl_xor_sync(0xffffffffu, bdh, off));
    }

    float lsum = 0.f;
    if (t == 0) {
        int bi0 = __float_as_uint(bd0) & 1023;
        int bih = __float_as_uint(bdh) & 1023;
        int rl = m0 + g;
        int grow = row0 + rl;
        // exact fp32 recompute of the winning distances
        float zn0 = 0.f, dt0 = 0.f, zn1 = 0.f, dt1 = 0.f;
        const float* cb0 = cb + bi0 * DD;
        const float* cb1 = cb + bih * DD;
#pragma unroll
        for (int k = 0; k < DD; k++) {
            float z0 = zsm[rl * 33 + k];
            float z1 = zsm[(rl + 8) * 33 + k];
            zn0 += z0 * z0; dt0 = fmaf(z0, cb0[k], dt0);
            zn1 += z1 * z1; dt1 = fmaf(z1, cb1[k], dt1);
        }
        lsum = (zn0 + g_cbnorm[bi0] - 2.f * dt0) + (zn1 + g_cbnorm[bih] - 2.f * dt1);
        g_topic[grow] = bi0;
        g_topic[grow + 8] = bih;
        atomicAdd(&g_count[bi0], 1);
        atomicAdd(&g_count[bih], 1);
    }
#pragma unroll
    for (int off = 16; off; off >>= 1) lsum += __shfl_xor_sync(0xffffffffu, lsum, off);
    if (lane == 0) atomicAdd(&g_zloss, lsum);
}

// ---------------- decoder BN stats via topic histogram ----------------
__global__ __launch_bounds__(128) void k_decstats(const float* __restrict__ G,
                                                  const float* __restrict__ BE) {
    __shared__ float cnt[KC];
    int tid = threadIdx.x;
#pragma unroll
    for (int i = 0; i < 8; i++) cnt[tid + i * 128] = (float)g_count[tid + i * 128];
    __syncthreads();
    float s = 0.f, sq = 0.f;
    for (int k = 0; k < KC; k++) {
        float v = g_cbproj[k * HD + tid];
        float c = cnt[k];
        s += c * v;
        sq += c * v * v;
    }
    float mean = s * (1.f / (float)NR);
    float var  = sq * (1.f / (float)NR) - mean * mean;
    float sc = G[tid] * rsqrtf(var + EPSBN);
    g_dscale[tid] = sc;
    g_dshift[tid] = BE[tid] - mean * sc;
}

// ---------------- decoded = relu(bn(cbproj)) @ dec_w2 + b2  [1024,512] -----
__global__ __launch_bounds__(256) void k_decoded(const float* __restrict__ W2,
                                                 const float* __restrict__ B2) {
    __shared__ float as[16][HD];
    int tid = threadIdx.x;
    int k0 = blockIdx.x * 16;
#pragma unroll
    for (int i = 0; i < 8; i++) {
        int idx = tid + i * 256;
        int r = idx >> 7, j = idx & 127;
        float v = g_cbproj[(k0 + r) * HD + j];
        as[r][j] = fmaxf(fmaf(v, g_dscale[j], g_dshift[j]), 0.f);
    }
    __syncthreads();
    float acc0[16] = {}, acc1[16] = {};
    int c0 = tid, c1 = tid + 256;
    for (int j = 0; j < HD; j++) {
        float w0 = W2[j * DIN + c0];
        float w1 = W2[j * DIN + c1];
#pragma unroll
        for (int r = 0; r < 16; r++) {
            float a = as[r][j];
            acc0[r] = fmaf(a, w0, acc0[r]);
            acc1[r] = fmaf(a, w1, acc1[r]);
        }
    }
    float b0 = B2[c0], b1 = B2[c1];
#pragma unroll
    for (int r = 0; r < 16; r++) {
        g_decoded[(k0 + r) * DIN + c0] = acc0[r] + b0;
        g_decoded[(k0 + r) * DIN + c1] = acc1[r] + b1;
    }
}

// ---------------- recon: sum over all elements of (decoded[topic]-X)^2 -----
// 4 rows in flight per warp -> 32 outstanding float4 loads
__global__ __launch_bounds__(256) void k_recon(const float* __restrict__ X) {
    int warp = threadIdx.x >> 5, lane = threadIdx.x & 31;
    float lsum = 0.f;
    int row0 = blockIdx.x * 128 + warp * 16;
    for (int rr = 0; rr < 16; rr += 4) {
        const float4* xr[4];
        const float4* dr[4];
#pragma unroll
        for (int j = 0; j < 4; j++) {
            int row = row0 + rr + j;
            xr[j] = (const float4*)X + row * 128;
            dr[j] = (const float4*)g_decoded + g_topic[row] * 128;
        }
#pragma unroll
        for (int i = 0; i < 4; i++) {
#pragma unroll
            for (int j = 0; j < 4; j++) {
                float4 a = xr[j][lane + i * 32];
                float4 b = dr[j][lane + i * 32];
                float dx = a.x - b.x, dy = a.y - b.y, dz = a.z - b.z, dw = a.w - b.w;
                lsum += dx * dx + dy * dy + dz * dz + dw * dw;
            }
        }
    }
#pragma unroll
    for (int off = 16; off; off >>= 1) lsum += __shfl_xor_sync(0xffffffffu, lsum, off);
    if (lane == 0) atomicAdd(&g_recon, lsum);
}

// ---------------- final scalar: 2*zloss + sqrt(recon) ----------------
__global__ void k_final(float* __restrict__ out) {
    out[0] = 2.f * g_zloss + sqrtf(g_recon);
}

// ---------------- launcher ----------------
extern "C" void kernel_launch(void* const* d_in, const int* in_sizes, int n_in,
                              void* d_out, int out_size) {
    const float* X    = (const float*)d_in[0];
    const float* ew1  = (const float*)d_in[1];
    const float* eb1  = (const float*)d_in[2];
    const float* eg1  = (const float*)d_in[3];
    const float* ebe1 = (const float*)d_in[4];
    const float* ew2  = (const float*)d_in[5];
    const float* eb2  = (const float*)d_in[6];
    const float* dw1  = (const float*)d_in[7];
    const float* db1  = (const float*)d_in[8];
    const float* dg1  = (const float*)d_in[9];
    const float* dbe1 = (const float*)d_in[10];
    const float* dw2  = (const float*)d_in[11];
    const float* db2  = (const float*)d_in[12];
    const float* cb   = (const float*)d_in[13];

    // cbs 16384 + as4 16384 + wt4 2048 + zsm 8448 + cns 1024 words
    const int fusedSmem = (16384 + 16384 + 2048 + 8448 + 1024) * 4;
    cudaFuncSetAttribute(k_fused, cudaFuncAttributeMaxDynamicSharedMemorySize, fusedSmem);

    k_cbprep<<<KC, 128>>>(cb, dw1, db1);
    k_wprep<<<16, 256>>>(ew1);
    k_gemm1<<<NR / 128, 256>>>(X, eb1);
    k_bnfin<<<1, 128>>>(eg1, ebe1);
    k_fused<<<NR / 256, 512, fusedSmem>>>(cb, ew2, eb2);
    k_decstats<<<1, 128>>>(dg1, dbe1);
    k_decoded<<<KC / 16, 256>>>(dw2, db2);
    k_recon<<<NR / 128, 256>>>(X);
    k_final<<<1, 1>>>((float*)d_out);
}

// round 10
// speedup vs baseline: 1.1465x; 1.1465x over previous
#include <cuda_runtime.h>
#include <math.h>

// Problem sizes (fixed)
#define NR   65536
#define DIN  512
#define HD   128
#define DD   32
#define KC   1024
#define EPSBN 1e-5f

// ---------------- scratch (device globals; no allocations) ----------------
__device__ unsigned g_h1bf[NR * 64];     // encoder hidden pre-BN, bf16x2 (16.7 MB)
__device__ int      g_topic[NR];
__device__ float    g_colsum[HD];
__device__ float    g_colsumsq[HD];
__device__ float    g_escale[HD];
__device__ float    g_eshift[HD];
__device__ float    g_cbnorm[KC];
__device__ unsigned g_cbbf[KC * 16];     // codebook bf16x2 packed (linear pairs)
__device__ float    g_cbproj[KC * HD];   // codebook @ dec_w1 + dec_b1
__device__ int      g_count[KC];
__device__ float    g_dscale[HD];
__device__ float    g_dshift[HD];
__device__ float    g_decoded[KC * DIN]; // decoded codewords (2 MB)
__device__ float    g_zloss;
__device__ float    g_recon;

// ---------------- bf16 helpers ----------------
__device__ __forceinline__ unsigned f2bf2(float lo, float hi) {
    unsigned r;
    asm("cvt.rn.bf16x2.f32 %0, %1, %2;" : "=r"(r) : "f"(hi), "f"(lo));
    return r;
}
__device__ __forceinline__ float bflo(unsigned u) { return __uint_as_float(u << 16); }
__device__ __forceinline__ float bfhi(unsigned u) { return __uint_as_float(u & 0xffff0000u); }

__device__ __forceinline__ void mma_bf16(float& c0, float& c1, float& c2, float& c3,
                                         unsigned a0, unsigned a1, unsigned a2, unsigned a3,
                                         unsigned b0, unsigned b1) {
    asm volatile(
        "mma.sync.aligned.m16n8k16.row.col.f32.bf16.bf16.f32 "
        "{%0,%1,%2,%3},{%4,%5,%6,%7},{%8,%9},{%0,%1,%2,%3};"
        : "+f"(c0), "+f"(c1), "+f"(c2), "+f"(c3)
        : "r"(a0), "r"(a1), "r"(a2), "r"(a3), "r"(b0), "r"(b1));
}

// ------ cbprep: init accumulators + norms + bf16 pack + cbproj (1 kernel) --
__global__ __launch_bounds__(128) void k_cbprep(const float* __restrict__ cb,
                                                const float* __restrict__ W1,
                                                const float* __restrict__ B1) {
    __shared__ float row[DD];
    int tid = threadIdx.x, k = blockIdx.x;
    if (tid == 0) g_count[k] = 0;
    if (k == 0) {
        if (tid < HD) { g_colsum[tid] = 0.f; g_colsumsq[tid] = 0.f; }
        if (tid == 0) { g_zloss = 0.f; g_recon = 0.f; }
    }
    if (tid < 8) ((float4*)row)[tid] = ((const float4*)cb)[k * 8 + tid];
    __syncthreads();
    if (tid < 32) {
        float v = row[tid];
        if (tid < 16) g_cbbf[k * 16 + tid] = f2bf2(row[2 * tid], row[2 * tid + 1]);
        float s = v * v;
#pragma unroll
        for (int off = 16; off; off >>= 1) s += __shfl_xor_sync(0xffffffffu, s, off);
        if (tid == 0) g_cbnorm[k] = s;
    }
    float acc = B1[tid];
#pragma unroll
    for (int d = 0; d < DD; d++) acc = fmaf(row[d], W1[d * HD + tid], acc);
    g_cbproj[k * HD + tid] = acc;
}

// ------- GEMM1 (bf16 mma) + fused column stats: h1 = X@W + b --------------
// (exact R8 version — proven) double-buffered smem, one sync per chunk.
__global__ __launch_bounds__(256, 2) void k_gemm1(const float* __restrict__ X,
                                                  const float* __restrict__ W,
                                                  const float* __restrict__ Bb) {
    __shared__ unsigned xs[2][128 * 20];
    __shared__ unsigned wts[2][128 * 20];
    __shared__ float ss[HD], ssq[HD];
    int tid = threadIdx.x, lane = tid & 31, warp = tid >> 5;
    int g = lane >> 2, t = lane & 3;
    int row0 = blockIdx.x * 128;
    int m0 = (warp >> 1) * 32;
    int n0w = (warp & 1) * 64;

    if (tid < HD) { ss[tid] = 0.f; ssq[tid] = 0.f; }

    float c[2][8][4];
#pragma unroll
    for (int i = 0; i < 2; i++)
#pragma unroll
        for (int j = 0; j < 8; j++)
#pragma unroll
            for (int q = 0; q < 4; q++) c[i][j][q] = 0.f;

    int xr = tid >> 1, xk = (tid & 1) * 16;     // floats
    const float* Xp = X + (row0 + xr) * DIN + xk;
    int wn = tid & 127, wk0 = (tid >> 7) * 16;  // floats

    // load + stage chunk 0 into buffer 0
    float4 xv[4];
    float wv[16];
#pragma unroll
    for (int i = 0; i < 4; i++) xv[i] = *(const float4*)(Xp + 4 * i);
#pragma unroll
    for (int j = 0; j < 16; j++) wv[j] = W[(wk0 + j) * HD + wn];
#pragma unroll
    for (int i = 0; i < 4; i++) {
        xs[0][xr * 20 + (xk >> 1) + 2 * i]     = f2bf2(xv[i].x, xv[i].y);
        xs[0][xr * 20 + (xk >> 1) + 2 * i + 1] = f2bf2(xv[i].z, xv[i].w);
    }
#pragma unroll
    for (int i = 0; i < 8; i++)
        wts[0][wn * 20 + (wk0 >> 1) + i] = f2bf2(wv[2 * i], wv[2 * i + 1]);
    __syncthreads();

    int p = 0;
    for (int kk = 0; kk < DIN; kk += 32) {
        bool more = (kk + 32 < DIN);
        if (more) {
#pragma unroll
            for (int i = 0; i < 4; i++) xv[i] = *(const float4*)(Xp + kk + 32 + 4 * i);
#pragma unroll
            for (int j = 0; j < 16; j++) wv[j] = W[(kk + 32 + wk0 + j) * HD + wn];
        }

#pragma unroll
        for (int s = 0; s < 2; s++) {
            unsigned a[2][4];
#pragma unroll
            for (int mt = 0; mt < 2; mt++) {
                int mr = m0 + mt * 16 + g;
                a[mt][0] = xs[p][mr * 20 + 8 * s + t];
                a[mt][1] = xs[p][(mr + 8) * 20 + 8 * s + t];
                a[mt][2] = xs[p][mr * 20 + 8 * s + t + 4];
                a[mt][3] = xs[p][(mr + 8) * 20 + 8 * s + t + 4];
            }
#pragma unroll
            for (int nt = 0; nt < 8; nt++) {
                int nc = n0w + nt * 8 + g;
                unsigned b0 = wts[p][nc * 20 + 8 * s + t];
                unsigned b1 = wts[p][nc * 20 + 8 * s + t + 4];
                mma_bf16(c[0][nt][0], c[0][nt][1], c[0][nt][2], c[0][nt][3],
                         a[0][0], a[0][1], a[0][2], a[0][3], b0, b1);
                mma_bf16(c[1][nt][0], c[1][nt][1], c[1][nt][2], c[1][nt][3],
                         a[1][0], a[1][1], a[1][2], a[1][3], b0, b1);
            }
        }

        if (more) {
            int q = p ^ 1;
#pragma unroll
            for (int i = 0; i < 4; i++) {
                xs[q][xr * 20 + (xk >> 1) + 2 * i]     = f2bf2(xv[i].x, xv[i].y);
                xs[q][xr * 20 + (xk >> 1) + 2 * i + 1] = f2bf2(xv[i].z, xv[i].w);
            }
#pragma unroll
            for (int i = 0; i < 8; i++)
                wts[q][wn * 20 + (wk0 >> 1) + i] = f2bf2(wv[2 * i], wv[2 * i + 1]);
        }
        __syncthreads();
        p ^= 1;
    }

    // epilogue: bias, bf16x2 store of h1, column stats (shfl-reduced)
    int r0 = row0 + m0 + g;
#pragma unroll
    for (int nt = 0; nt < 8; nt++) {
        int col = n0w + nt * 8 + 2 * t;
        int u = (n0w >> 1) + nt * 4 + t;
        float b0v = Bb[col], b1v = Bb[col + 1];
        float v00 = c[0][nt][0] + b0v, v01 = c[0][nt][1] + b1v;
        float v02 = c[0][nt][2] + b0v, v03 = c[0][nt][3] + b1v;
        float v10 = c[1][nt][0] + b0v, v11 = c[1][nt][1] + b1v;
        float v12 = c[1][nt][2] + b0v, v13 = c[1][nt][3] + b1v;
        g_h1bf[r0 * 64 + u]        = f2bf2(v00, v01);
        g_h1bf[(r0 + 8) * 64 + u]  = f2bf2(v02, v03);
        g_h1bf[(r0 + 16) * 64 + u] = f2bf2(v10, v11);
        g_h1bf[(r0 + 24) * 64 + u] = f2bf2(v12, v13);
        float s0 = v00 + v02 + v10 + v12;
        float s1 = v01 + v03 + v11 + v13;
        float q0 = v00 * v00 + v02 * v02 + v10 * v10 + v12 * v12;
        float q1 = v01 * v01 + v03 * v03 + v11 * v11 + v13 * v13;
#pragma unroll
        for (int off = 4; off <= 16; off <<= 1) {
            s0 += __shfl_xor_sync(0xffffffffu, s0, off);
            s1 += __shfl_xor_sync(0xffffffffu, s1, off);
            q0 += __shfl_xor_sync(0xffffffffu, q0, off);
            q1 += __shfl_xor_sync(0xffffffffu, q1, off);
        }
        if (g == 0) {
            atomicAdd(&ss[col],      s0);
            atomicAdd(&ss[col + 1],  s1);
            atomicAdd(&ssq[col],     q0);
            atomicAdd(&ssq[col + 1], q1);
        }
    }
    __syncthreads();
    if (tid < HD) {
        atomicAdd(&g_colsum[tid], ss[tid]);
        atomicAdd(&g_colsumsq[tid], ssq[tid]);
    }
}

__global__ void k_bnfin(const float* __restrict__ G, const float* __restrict__ BE) {
    int j = threadIdx.x;
    float mean = g_colsum[j] * (1.f / (float)NR);
    float var  = g_colsumsq[j] * (1.f / (float)NR) - mean * mean;
    float sc = G[j] * rsqrtf(var + EPSBN);
    g_escale[j] = sc;
    g_eshift[j] = BE[j] - mean * sc;
}

// ------ FUSED: z = relu(bn(h1)) @ W2 -> distance argmin (z never hits mem) -
// gemm2 part = R8 layout (proven); dist sweep = LDS.128 codebook + fmin argmin.
__global__ __launch_bounds__(512) void k_fused(const float* __restrict__ cb,
                                               const float* __restrict__ W2,
                                               const float* __restrict__ B2) {
    extern __shared__ unsigned fsm[];
    unsigned* cbs = fsm;                        // 1024 rows x 16 permuted pairs
    unsigned* as  = fsm + 16384;                // 256 x 68 (R8 layout)
    unsigned* wt  = fsm + 16384 + 17408;        // 32 x 68
    float* zsm = (float*)(fsm + 35968);         // 256 x 33 fp32
    float* cns = zsm + 256 * 33;                // 1024

    int tid = threadIdx.x, lane = tid & 31, warp = tid >> 5;
    int g = lane >> 2, t = lane & 3;
    int row0 = blockIdx.x * 256;

    // stage W2 -> [n][kpair] stride 68 (R8)
#pragma unroll
    for (int i = 0; i < 4; i++) {
        int idx = tid + i * 512;
        int n = idx & 31, kp = idx >> 5;
        wt[n * 68 + kp] = f2bf2(W2[(2 * kp) * DD + n], W2[(2 * kp + 1) * DD + n]);
    }
    // stage codebook -> permuted 16-word rows: pos(4*i4+q) = 4q + i4
#pragma unroll
    for (int i = 0; i < 8; i++) {
        int e = tid + i * 512;            // uint4 index (4096)
        uint4 u = ((const uint4*)g_cbbf)[e];
        int n = e >> 2, i4 = e & 3;
        cbs[n * 16 + i4 + 0]  = u.x;
        cbs[n * 16 + i4 + 4]  = u.y;
        cbs[n * 16 + i4 + 8]  = u.z;
        cbs[n * 16 + i4 + 12] = u.w;
    }
#pragma unroll
    for (int i = 0; i < 2; i++) cns[tid + i * 512] = g_cbnorm[tid + i * 512];
    // stage activations: bf16 h1 -> BN -> ReLU -> bf16, stride 68 (R8)
#pragma unroll
    for (int i = 0; i < 8; i++) {
        int e = tid + i * 512;            // uint4 index (4096)
        int r = e >> 4, kp0 = (e & 15) * 4;
        uint4 u = *(const uint4*)&g_h1bf[(row0 + r) * 64 + kp0];
        float4 sc0 = __ldg((const float4*)&g_escale[2 * kp0]);
        float4 sc1 = __ldg((const float4*)&g_escale[2 * kp0 + 4]);
        float4 sh0 = __ldg((const float4*)&g_eshift[2 * kp0]);
        float4 sh1 = __ldg((const float4*)&g_eshift[2 * kp0 + 4]);
        uint4 o;
        o.x = f2bf2(fmaxf(fmaf(bflo(u.x), sc0.x, sh0.x), 0.f),
                    fmaxf(fmaf(bfhi(u.x), sc0.y, sh0.y), 0.f));
        o.y = f2bf2(fmaxf(fmaf(bflo(u.y), sc0.z, sh0.z), 0.f),
                    fmaxf(fmaf(bfhi(u.y), sc0.w, sh0.w), 0.f));
        o.z = f2bf2(fmaxf(fmaf(bflo(u.z), sc1.x, sh1.x), 0.f),
                    fmaxf(fmaf(bfhi(u.z), sc1.y, sh1.y), 0.f));
        o.w = f2bf2(fmaxf(fmaf(bflo(u.w), sc1.z, sh1.z), 0.f),
                    fmaxf(fmaf(bfhi(u.w), sc1.w, sh1.w), 0.f));
        *(uint4*)&as[r * 68 + kp0] = o;
    }
    __syncthreads();

    // ---- gemm2: per-warp 16 rows, z[16 x 32] in C fragments (R8) ----
    int m0 = warp * 16;
    float c[4][4];
#pragma unroll
    for (int nt = 0; nt < 4; nt++)
#pragma unroll
        for (int q = 0; q < 4; q++) c[nt][q] = 0.f;
#pragma unroll
    for (int s = 0; s < 8; s++) {
        int mr = m0 + g;
        unsigned a0 = as[mr * 68 + 8 * s + t];
        unsigned a1 = as[(mr + 8) * 68 + 8 * s + t];
        unsigned a2 = as[mr * 68 + 8 * s + t + 4];
        unsigned a3 = as[(mr + 8) * 68 + 8 * s + t + 4];
#pragma unroll
        for (int nt = 0; nt < 4; nt++) {
            unsigned b0 = wt[(nt * 8 + g) * 68 + 8 * s + t];
            unsigned b1 = wt[(nt * 8 + g) * 68 + 8 * s + t + 4];
            mma_bf16(c[nt][0], c[nt][1], c[nt][2], c[nt][3], a0, a1, a2, a3, b0, b1);
        }
    }
    // bias; fp32 copy to zsm; repack C-frags into dist A-frags
    int ra = m0 + g, rb = m0 + 8 + g;
    unsigned za[2][4];
#pragma unroll
    for (int nt = 0; nt < 4; nt++) {
        int col = nt * 8 + 2 * t;
        float b0v = B2[col], b1v = B2[col + 1];
        c[nt][0] += b0v; c[nt][1] += b1v; c[nt][2] += b0v; c[nt][3] += b1v;
        zsm[ra * 33 + col]     = c[nt][0];
        zsm[ra * 33 + col + 1] = c[nt][1];
        zsm[rb * 33 + col]     = c[nt][2];
        zsm[rb * 33 + col + 1] = c[nt][3];
    }
#pragma unroll
    for (int s = 0; s < 2; s++) {
        za[s][0] = f2bf2(c[2 * s][0],     c[2 * s][1]);
        za[s][1] = f2bf2(c[2 * s][2],     c[2 * s][3]);
        za[s][2] = f2bf2(c[2 * s + 1][0], c[2 * s + 1][1]);
        za[s][3] = f2bf2(c[2 * s + 1][2], c[2 * s + 1][3]);
    }
    __syncwarp();   // zsm rows of this warp written by its own lanes only

    // ---- distance sweep: one LDS.128 per 8 codewords, fmin-packed argmin --
    float bd0 = 3.4e38f, bdh = 3.4e38f;
    int nb = g * 16 + 4 * t;
#pragma unroll 2
    for (int n0 = 0; n0 < KC / 8; n0++) {
        uint4 vb = *(const uint4*)&cbs[n0 * 128 + nb];
        float d0 = 0.f, d1 = 0.f, d2 = 0.f, d3 = 0.f;
        mma_bf16(d0, d1, d2, d3, za[0][0], za[0][1], za[0][2], za[0][3], vb.x, vb.y);
        mma_bf16(d0, d1, d2, d3, za[1][0], za[1][1], za[1][2], za[1][3], vb.z, vb.w);
        int col0 = n0 * 8 + 2 * t;
        float2 cn = *(const float2*)&cns[col0];
        float e0 = fmaf(d0, -2.f, cn.x), e1 = fmaf(d1, -2.f, cn.y);
        float f0 = fmaf(d2, -2.f, cn.x), f1 = fmaf(d3, -2.f, cn.y);
        bd0 = fminf(bd0, __uint_as_float((__float_as_uint(e0) & 0xfffffc00u) | col0));
        bd0 = fminf(bd0, __uint_as_float((__float_as_uint(e1) & 0xfffffc00u) | (col0 + 1)));
        bdh = fminf(bdh, __uint_as_float((__float_as_uint(f0) & 0xfffffc00u) | col0));
        bdh = fminf(bdh, __uint_as_float((__float_as_uint(f1) & 0xfffffc00u) | (col0 + 1)));
    }
#pragma unroll
    for (int off = 1; off <= 2; off <<= 1) {
        bd0 = fminf(bd0, __shfl_xor_sync(0xffffffffu, bd0, off));
        bdh = fminf(bdh, __shfl_xor_sync(0xffffffffu, bdh, off));
    }

    float lsum = 0.f;
    if (t == 0) {
        int bi0 = __float_as_uint(bd0) & 1023;
        int bih = __float_as_uint(bdh) & 1023;
        int rl = m0 + g;
        int grow = row0 + rl;
        // exact fp32 recompute of the winning distances
        float zn0 = 0.f, dt0 = 0.f, zn1 = 0.f, dt1 = 0.f;
        const float* cb0 = cb + bi0 * DD;
        const float* cb1 = cb + bih * DD;
#pragma unroll
        for (int k = 0; k < DD; k++) {
            float z0 = zsm[rl * 33 + k];
            float z1 = zsm[(rl + 8) * 33 + k];
            zn0 += z0 * z0; dt0 = fmaf(z0, cb0[k], dt0);
            zn1 += z1 * z1; dt1 = fmaf(z1, cb1[k], dt1);
        }
        lsum = (zn0 + g_cbnorm[bi0] - 2.f * dt0) + (zn1 + g_cbnorm[bih] - 2.f * dt1);
        g_topic[grow] = bi0;
        g_topic[grow + 8] = bih;
        atomicAdd(&g_count[bi0], 1);
        atomicAdd(&g_count[bih], 1);
    }
#pragma unroll
    for (int off = 16; off; off >>= 1) lsum += __shfl_xor_sync(0xffffffffu, lsum, off);
    if (lane == 0) atomicAdd(&g_zloss, lsum);
}

// ---------------- decoder BN stats via topic histogram ----------------
__global__ __launch_bounds__(128) void k_decstats(const float* __restrict__ G,
                                                  const float* __restrict__ BE) {
    __shared__ float cnt[KC];
    int tid = threadIdx.x;
#pragma unroll
    for (int i = 0; i < 8; i++) cnt[tid + i * 128] = (float)g_count[tid + i * 128];
    __syncthreads();
    float s = 0.f, sq = 0.f;
    for (int k = 0; k < KC; k++) {
        float v = g_cbproj[k * HD + tid];
        float c = cnt[k];
        s += c * v;
        sq += c * v * v;
    }
    float mean = s * (1.f / (float)NR);
    float var  = sq * (1.f / (float)NR) - mean * mean;
    float sc = G[tid] * rsqrtf(var + EPSBN);
    g_dscale[tid] = sc;
    g_dshift[tid] = BE[tid] - mean * sc;
}

// ---------------- decoded = relu(bn(cbproj)) @ dec_w2 + b2  [1024,512] -----
__global__ __launch_bounds__(256) void k_decoded(const float* __restrict__ W2,
                                                 const float* __restrict__ B2) {
    __shared__ float as[16][HD];
    int tid = threadIdx.x;
    int k0 = blockIdx.x * 16;
#pragma unroll
    for (int i = 0; i < 8; i++) {
        int idx = tid + i * 256;
        int r = idx >> 7, j = idx & 127;
        float v = g_cbproj[(k0 + r) * HD + j];
        as[r][j] = fmaxf(fmaf(v, g_dscale[j], g_dshift[j]), 0.f);
    }
    __syncthreads();
    float acc0[16] = {}, acc1[16] = {};
    int c0 = tid, c1 = tid + 256;
    for (int j = 0; j < HD; j++) {
        float w0 = W2[j * DIN + c0];
        float w1 = W2[j * DIN + c1];
#pragma unroll
        for (int r = 0; r < 16; r++) {
            float a = as[r][j];
            acc0[r] = fmaf(a, w0, acc0[r]);
            acc1[r] = fmaf(a, w1, acc1[r]);
        }
    }
    float b0 = B2[c0], b1 = B2[c1];
#pragma unroll
    for (int r = 0; r < 16; r++) {
        g_decoded[(k0 + r) * DIN + c0] = acc0[r] + b0;
        g_decoded[(k0 + r) * DIN + c1] = acc1[r] + b1;
    }
}

// ---------------- recon: sum over all elements of (decoded[topic]-X)^2 -----
// 4 rows in flight per warp -> 32 outstanding float4 loads
__global__ __launch_bounds__(256) void k_recon(const float* __restrict__ X) {
    int warp = threadIdx.x >> 5, lane = threadIdx.x & 31;
    float lsum = 0.f;
    int row0 = blockIdx.x * 128 + warp * 16;
    for (int rr = 0; rr < 16; rr += 4) {
        const float4* xr[4];
        const float4* dr[4];
#pragma unroll
        for (int j = 0; j < 4; j++) {
            int row = row0 + rr + j;
            xr[j] = (const float4*)X + row * 128;
            dr[j] = (const float4*)g_decoded + g_topic[row] * 128;
        }
#pragma unroll
        for (int i = 0; i < 4; i++) {
#pragma unroll
            for (int j = 0; j < 4; j++) {
                float4 a = xr[j][lane + i * 32];
                float4 b = dr[j][lane + i * 32];
                float dx = a.x - b.x, dy = a.y - b.y, dz = a.z - b.z, dw = a.w - b.w;
                lsum += dx * dx + dy * dy + dz * dz + dw * dw;
            }
        }
    }
#pragma unroll
    for (int off = 16; off; off >>= 1) lsum += __shfl_xor_sync(0xffffffffu, lsum, off);
    if (lane == 0) atomicAdd(&g_recon, lsum);
}

// ---------------- final scalar: 2*zloss + sqrt(recon) ----------------
__global__ void k_final(float* __restrict__ out) {
    out[0] = 2.f * g_zloss + sqrtf(g_recon);
}

// ---------------- launcher ----------------
extern "C" void kernel_launch(void* const* d_in, const int* in_sizes, int n_in,
                              void* d_out, int out_size) {
    const float* X    = (const float*)d_in[0];
    const float* ew1  = (const float*)d_in[1];
    const float* eb1  = (const float*)d_in[2];
    const float* eg1  = (const float*)d_in[3];
    const float* ebe1 = (const float*)d_in[4];
    const float* ew2  = (const float*)d_in[5];
    const float* eb2  = (const float*)d_in[6];
    const float* dw1  = (const float*)d_in[7];
    const float* db1  = (const float*)d_in[8];
    const float* dg1  = (const float*)d_in[9];
    const float* dbe1 = (const float*)d_in[10];
    const float* dw2  = (const float*)d_in[11];
    const float* db2  = (const float*)d_in[12];
    const float* cb   = (const float*)d_in[13];

    // cbs 16384 + as 17408 + wt 2176 + zsm 8448 + cns 1024 words
    const int fusedSmem = (16384 + 17408 + 2176 + 8448 + 1024) * 4;
    cudaFuncSetAttribute(k_fused, cudaFuncAttributeMaxDynamicSharedMemorySize, fusedSmem);

    k_cbprep<<<KC, 128>>>(cb, dw1, db1);
    k_gemm1<<<NR / 128, 256>>>(X, ew1, eb1);
    k_bnfin<<<1, 128>>>(eg1, ebe1);
    k_fused<<<NR / 256, 512, fusedSmem>>>(cb, ew2, eb2);
    k_decstats<<<1, 128>>>(dg1, dbe1);
    k_decoded<<<KC / 16, 256>>>(dw2, db2);
    k_recon<<<NR / 128, 256>>>(X);
    k_final<<<1, 1>>>((float*)d_out);
}